// round 3
// baseline (speedup 1.0000x reference)
#include <cuda_runtime.h>
#include <cstdint>

#define N_ROWS 1000000
#define NTHREADS 256
#define ROWS_PER_WARP 64
#define WARPS 8
#define TILE_ROWS (ROWS_PER_WARP * WARPS)                    // 512
#define NBLOCKS ((N_ROWS + TILE_ROWS - 1) / TILE_ROWS)       // 1954

// SMEM: W tiles [3][64k][64n] swizzled = 3*16384 B, then per-warp A [64][64] = 8*16384 B
#define SMEM_W_BYTES  49152
#define SMEM_A_BYTES  131072
#define SMEM_TOTAL    (SMEM_W_BYTES + SMEM_A_BYTES)          // 180224

__device__ __forceinline__ uint32_t tf32r(float f) {
    uint32_t u;
    asm("cvt.rna.tf32.f32 %0, %1;" : "=r"(u) : "f"(f));
    return u;
}

// m16n8k8 tf32 mma, D accumulates in place.
__device__ __forceinline__ void mma1688(float* d, const uint32_t* a, uint32_t b0, uint32_t b1) {
    asm volatile(
        "mma.sync.aligned.m16n8k8.row.col.f32.tf32.tf32.f32 "
        "{%0,%1,%2,%3}, {%4,%5,%6,%7}, {%8,%9}, {%0,%1,%2,%3};"
        : "+f"(d[0]), "+f"(d[1]), "+f"(d[2]), "+f"(d[3])
        : "r"(a[0]), "r"(a[1]), "r"(a[2]), "r"(a[3]), "r"(b0), "r"(b1));
}

__global__ void __launch_bounds__(NTHREADS, 1)
polyconv_kernel(const float* __restrict__ x,
                const int* __restrict__ li,
                const int* __restrict__ ri,
                const float* __restrict__ W,
                const float* __restrict__ bias,
                float* __restrict__ out) {
    extern __shared__ char smem[];
    uint32_t* sW = reinterpret_cast<uint32_t*>(smem);                       // [3][64][64]
    const int tid = threadIdx.x;
    const int w = tid >> 5;
    const int l = tid & 31;
    uint32_t* sA = reinterpret_cast<uint32_t*>(smem + SMEM_W_BYTES + w * 16384);  // [64][64]

    // ---- one-time per CTA: stage W into swizzled B tiles.
    // gmem W[o][t*64+d] -> sW[t][k=d][n' = o ^ ((d&3)<<3)]  (tf32-rounded)
    for (int i = tid; i < 3 * 64 * 64; i += NTHREADS) {
        const int t = i >> 12;
        const int d = (i >> 6) & 63;
        const int o = i & 63;
        sW[t * 4096 + d * 64 + (o ^ ((d & 3) << 3))] = tf32r(W[o * 192 + t * 64 + d]);
    }
    __syncthreads();

    const int base = blockIdx.x * TILE_ROWS + w * ROWS_PER_WARP;

    float acc[4][8][4];
#pragma unroll
    for (int m = 0; m < 4; m++)
#pragma unroll
        for (int nb = 0; nb < 8; nb++)
#pragma unroll
            for (int j = 0; j < 4; j++) acc[m][nb][j] = 0.0f;

    const int gsub = l >> 4;   // 0/1: which of 2 rows per copy step
    const int c4 = l & 15;     // 16B chunk within a 256B row
    const int q = l & 3;       // threadID_in_group
    const int gg = l >> 2;     // groupID
    const uint32_t asw = (uint32_t)gg << 2;  // A swizzle term: (row&7)<<2, row&7 == gg

#pragma unroll 1
    for (int t = 0; t < 3; t++) {
        const int* __restrict__ ip = (t == 1) ? li : ri;
        // ---- gather-stage 64 rows (x / x[L] / x[R]) into swizzled sA ----
#pragma unroll 4
        for (int i = 0; i < 32; i++) {
            const int row = 2 * i + gsub;          // row within warp tile
            int grow = base + row;
            if (grow >= N_ROWS) grow = N_ROWS - 1; // clamp (stores guarded later)
            const int src = (t == 0) ? grow : ip[grow];
            const float4 v = *reinterpret_cast<const float4*>(x + (size_t)src * 64 + c4 * 4);
            const uint32_t col4 = (uint32_t)(c4 * 4) ^ ((uint32_t)(row & 7) << 2);
            uint4 u;
            u.x = tf32r(v.x); u.y = tf32r(v.y); u.z = tf32r(v.z); u.w = tf32r(v.w);
            *reinterpret_cast<uint4*>(sA + row * 64 + col4) = u;
        }
        __syncwarp();

        // ---- 4 m-tiles x 8 n-blocks x 8 k-steps of m16n8k8 tf32 mma ----
        const uint32_t* sWt = sW + t * 4096;
#pragma unroll
        for (int ks = 0; ks < 8; ks++) {
            const int c0 = ks * 8 + q;
            const uint32_t sc0 = (uint32_t)c0 ^ asw;
            const uint32_t sc1 = (uint32_t)(c0 + 4) ^ asw;
            uint32_t a[4][4];
#pragma unroll
            for (int m = 0; m < 4; m++) {
                const int r0 = m * 16 + gg;
                a[m][0] = sA[r0 * 64 + sc0];
                a[m][1] = sA[(r0 + 8) * 64 + sc0];
                a[m][2] = sA[r0 * 64 + sc1];
                a[m][3] = sA[(r0 + 8) * 64 + sc1];
            }
            const uint32_t bsw = (uint32_t)q << 3;  // (k&3)<<3 (same for k0 and k0+4)
#pragma unroll
            for (int nb = 0; nb < 8; nb++) {
                const uint32_t n = (uint32_t)(nb * 8 + gg) ^ bsw;
                const uint32_t b0 = sWt[c0 * 64 + n];
                const uint32_t b1 = sWt[(c0 + 4) * 64 + n];
#pragma unroll
                for (int m = 0; m < 4; m++) mma1688(acc[m][nb], a[m], b0, b1);
            }
        }
        __syncwarp();   // done reading sA before next t overwrites it
    }

    // ---- epilogue: add bias, direct STG.64 ----
#pragma unroll
    for (int nb = 0; nb < 8; nb++) {
        const int col = nb * 8 + q * 2;
        const float2 bb = *reinterpret_cast<const float2*>(bias + col);
#pragma unroll
        for (int m = 0; m < 4; m++) {
            const int r0 = base + m * 16 + gg;
            if (r0 < N_ROWS) {
                float2 v;
                v.x = acc[m][nb][0] + bb.x;
                v.y = acc[m][nb][1] + bb.y;
                *reinterpret_cast<float2*>(out + (size_t)r0 * 64 + col) = v;
            }
            const int r1 = r0 + 8;
            if (r1 < N_ROWS) {
                float2 v;
                v.x = acc[m][nb][2] + bb.x;
                v.y = acc[m][nb][3] + bb.y;
                *reinterpret_cast<float2*>(out + (size_t)r1 * 64 + col) = v;
            }
        }
    }
}

extern "C" void kernel_launch(void* const* d_in, const int* in_sizes, int n_in,
                              void* d_out, int out_size) {
    const float* x  = (const float*)d_in[0];
    const int*   li = (const int*)d_in[1];
    const int*   ri = (const int*)d_in[2];
    const float* W  = (const float*)d_in[3];
    const float* b  = (const float*)d_in[4];
    float* out = (float*)d_out;

    cudaFuncSetAttribute(polyconv_kernel,
                         cudaFuncAttributeMaxDynamicSharedMemorySize, SMEM_TOTAL);
    polyconv_kernel<<<NBLOCKS, NTHREADS, SMEM_TOTAL>>>(x, li, ri, W, b, out);
}